// round 4
// baseline (speedup 1.0000x reference)
#include <cuda_runtime.h>

// Live computation: out = MLP( (mean_p lidar[b,p,:]) @ wv ).
// Attention is dead (zero-pad query row -> uniform softmax -> mean of V).
// Further fold: h1 = lrelu(mean @ (wv@wo1) + b1), so precompute W2 = wv@wo1
// ([256,128]) concurrently with the DRAM-bound lidar reduction.
//
// One fused launch, 280 blocks x 1024 threads:
//   bid [0,256)   : lidar partial sums (16 batches x 16 splits)  -> g_partial
//   bid [256,264) : W2 = wv @ wo1 (8 blocks x 32 rows)           -> g_W2
//   bid [264,280) : per-batch head; spins on g_sync until the 264
//                   producer blocks arrive, then mean->h1->h2->out.

#define BATCH     16
#define N_POINTS  4096
#define LIDAR_C   256
#define C4        (LIDAR_C / 4)        // 64
#define D_MODEL   1024
#define H1        128
#define BIN_SIZE  256
#define SPLIT     16
#define PTS_PER_SPLIT (N_POINTS / SPLIT)  // 256

#define REDUCE_BLOCKS (BATCH * SPLIT)     // 256
#define FUSE_BLOCKS   8
#define HEAD_BLOCKS   BATCH               // 16
#define TOTAL_BLOCKS  (REDUCE_BLOCKS + FUSE_BLOCKS + HEAD_BLOCKS)  // 280
#define ARRIVALS      (REDUCE_BLOCKS + FUSE_BLOCKS)                // 264

__device__ float4       g_partial[SPLIT * BATCH * C4];   // 256 KB
__device__ float4       g_W2[LIDAR_C * (H1 / 4)];        // [256][32] f4
__device__ unsigned int g_sync;

__global__ void __launch_bounds__(1024, 1)
fused_kernel(const float4* __restrict__ lidar4,   // [16][4096][64] f4
             const float*  __restrict__ wv,       // [256][1024]
             const float4* __restrict__ wo14,     // [1024][32] f4
             const float4* __restrict__ b14,      // [32] f4
             const float4* __restrict__ wo24,     // [128][32] f4
             const float4* __restrict__ b24,      // [32] f4
             const float4* __restrict__ wo34,     // [128][64] f4
             const float4* __restrict__ b34,      // [64] f4
             float4*       __restrict__ out4)     // [16][64] f4
{
    const int bid = blockIdx.x;
    const int tid = threadIdx.x;

    if (bid < REDUCE_BLOCKS) {
        // ================= lidar partial sums (DRAM-bound) =================
        const int b = bid >> 4;
        const int s = bid & 15;
        const int c4 = tid & 63;
        const int r  = tid >> 6;                  // 16 row-groups x 16 rows

        const float4* base = lidar4
            + ((size_t)b * N_POINTS + (size_t)s * PTS_PER_SPLIT + (size_t)r * 16) * C4 + c4;

        float4 acc = make_float4(0.f, 0.f, 0.f, 0.f);
#pragma unroll
        for (int i = 0; i < 16; ++i) {
            float4 v = base[(size_t)i * C4];
            acc.x += v.x; acc.y += v.y; acc.z += v.z; acc.w += v.w;
        }

        __shared__ float4 sp[16][C4];
        sp[r][c4] = acc;
        __syncthreads();

        if (r == 0) {
            float4 t = make_float4(0.f, 0.f, 0.f, 0.f);
            float4 u = make_float4(0.f, 0.f, 0.f, 0.f);
#pragma unroll
            for (int g = 0; g < 16; g += 2) {
                float4 a = sp[g][c4], bb = sp[g + 1][c4];
                t.x += a.x; t.y += a.y; t.z += a.z; t.w += a.w;
                u.x += bb.x; u.y += bb.y; u.z += bb.z; u.w += bb.w;
            }
            t.x += u.x; t.y += u.y; t.z += u.z; t.w += u.w;
            g_partial[((size_t)s * BATCH + b) * C4 + c4] = t;
        }

        __syncthreads();
        __threadfence();
        if (tid == 0) atomicAdd(&g_sync, 1u);

    } else if (bid < REDUCE_BLOCKS + FUSE_BLOCKS) {
        // ================= W2 = wv @ wo1 (overlaps the reduce) =============
        const int c  = (bid - REDUCE_BLOCKS) * 32 + (tid >> 5);  // 0..255
        const int j4 = tid & 31;

        const float*  wrow = wv + (size_t)c * D_MODEL;
        float4 a0 = make_float4(0.f, 0.f, 0.f, 0.f);
        float4 a1 = make_float4(0.f, 0.f, 0.f, 0.f);
        float4 a2 = make_float4(0.f, 0.f, 0.f, 0.f);
        float4 a3 = make_float4(0.f, 0.f, 0.f, 0.f);
#pragma unroll 4
        for (int k = 0; k < D_MODEL; k += 4) {
            float s0 = __ldg(&wrow[k + 0]);
            float s1 = __ldg(&wrow[k + 1]);
            float s2 = __ldg(&wrow[k + 2]);
            float s3 = __ldg(&wrow[k + 3]);
            float4 w0 = __ldg(&wo14[(size_t)(k + 0) * 32 + j4]);
            float4 w1 = __ldg(&wo14[(size_t)(k + 1) * 32 + j4]);
            float4 w2 = __ldg(&wo14[(size_t)(k + 2) * 32 + j4]);
            float4 w3 = __ldg(&wo14[(size_t)(k + 3) * 32 + j4]);
            a0.x += s0 * w0.x; a0.y += s0 * w0.y; a0.z += s0 * w0.z; a0.w += s0 * w0.w;
            a1.x += s1 * w1.x; a1.y += s1 * w1.y; a1.z += s1 * w1.z; a1.w += s1 * w1.w;
            a2.x += s2 * w2.x; a2.y += s2 * w2.y; a2.z += s2 * w2.z; a2.w += s2 * w2.w;
            a3.x += s3 * w3.x; a3.y += s3 * w3.y; a3.z += s3 * w3.z; a3.w += s3 * w3.w;
        }
        float4 t;
        t.x = (a0.x + a1.x) + (a2.x + a3.x);
        t.y = (a0.y + a1.y) + (a2.y + a3.y);
        t.z = (a0.z + a1.z) + (a2.z + a3.z);
        t.w = (a0.w + a1.w) + (a2.w + a3.w);
        g_W2[(size_t)c * 32 + j4] = t;

        __syncthreads();
        __threadfence();
        if (tid == 0) atomicAdd(&g_sync, 1u);

    } else {
        // ================= per-batch head ==================================
        const int b = bid - (REDUCE_BLOCKS + FUSE_BLOCKS);

        __shared__ float4 s_red[1024];    // 16 KB, reused per stage
        __shared__ float  s_mean[LIDAR_C];
        __shared__ float  s_h1[H1];
        __shared__ float  s_h2[H1];

        // wait for all producers
        if (tid == 0) {
            volatile unsigned int* p = &g_sync;
            while (*p < ARRIVALS) __nanosleep(64);
        }
        __syncthreads();
        __threadfence();

        // ---- fold 16 partials -> mean (exactly 1 f4 load per thread) ------
        {
            const int c4 = tid & 63;
            const int sg = tid >> 6;      // 0..15
            s_red[sg * C4 + c4] = g_partial[((size_t)sg * BATCH + b) * C4 + c4];
        }
        __syncthreads();
        if (tid < C4) {
            float4 t = make_float4(0.f, 0.f, 0.f, 0.f);
#pragma unroll
            for (int g = 0; g < 16; ++g) {
                float4 v = s_red[g * C4 + tid];
                t.x += v.x; t.y += v.y; t.z += v.z; t.w += v.w;
            }
            const float inv = 1.0f / (float)N_POINTS;
            s_mean[tid * 4 + 0] = t.x * inv;
            s_mean[tid * 4 + 1] = t.y * inv;
            s_mean[tid * 4 + 2] = t.z * inv;
            s_mean[tid * 4 + 3] = t.w * inv;
        }
        __syncthreads();

        // ---- h1 = lrelu(mean @ W2 + b1): 32 j4 x 32 kg of 8 k -------------
        {
            const int j4 = tid & 31;
            const int kg = tid >> 5;      // 0..31
            float4 acc = make_float4(0.f, 0.f, 0.f, 0.f);
#pragma unroll
            for (int i = 0; i < 8; ++i) {
                const int k = kg * 8 + i;
                float4 w = g_W2[(size_t)k * 32 + j4];
                float  s = s_mean[k];
                acc.x += s * w.x; acc.y += s * w.y; acc.z += s * w.z; acc.w += s * w.w;
            }
            s_red[kg * 32 + j4] = acc;
        }
        __syncthreads();
        if (tid < 32) {
            float4 acc = __ldg(&b14[tid]);
#pragma unroll
            for (int g = 0; g < 32; ++g) {
                float4 v = s_red[g * 32 + tid];
                acc.x += v.x; acc.y += v.y; acc.z += v.z; acc.w += v.w;
            }
            s_h1[tid * 4 + 0] = (acc.x > 0.f) ? acc.x : 0.01f * acc.x;
            s_h1[tid * 4 + 1] = (acc.y > 0.f) ? acc.y : 0.01f * acc.y;
            s_h1[tid * 4 + 2] = (acc.z > 0.f) ? acc.z : 0.01f * acc.z;
            s_h1[tid * 4 + 3] = (acc.w > 0.f) ? acc.w : 0.01f * acc.w;
        }
        __syncthreads();

        // ---- h2 = lrelu(h1 @ wo2 + b2): 32 j4 x 32 kg of 4 k --------------
        {
            const int j4 = tid & 31;
            const int kg = tid >> 5;
            float4 acc = make_float4(0.f, 0.f, 0.f, 0.f);
#pragma unroll
            for (int i = 0; i < 4; ++i) {
                const int k = kg * 4 + i;
                float4 w = __ldg(&wo24[(size_t)k * 32 + j4]);
                float  s = s_h1[k];
                acc.x += s * w.x; acc.y += s * w.y; acc.z += s * w.z; acc.w += s * w.w;
            }
            s_red[kg * 32 + j4] = acc;
        }
        __syncthreads();
        if (tid < 32) {
            float4 acc = __ldg(&b24[tid]);
#pragma unroll
            for (int g = 0; g < 32; ++g) {
                float4 v = s_red[g * 32 + tid];
                acc.x += v.x; acc.y += v.y; acc.z += v.z; acc.w += v.w;
            }
            s_h2[tid * 4 + 0] = (acc.x > 0.f) ? acc.x : 0.01f * acc.x;
            s_h2[tid * 4 + 1] = (acc.y > 0.f) ? acc.y : 0.01f * acc.y;
            s_h2[tid * 4 + 2] = (acc.z > 0.f) ? acc.z : 0.01f * acc.z;
            s_h2[tid * 4 + 3] = (acc.w > 0.f) ? acc.w : 0.01f * acc.w;
        }
        __syncthreads();

        // ---- out = h2 @ wo3 + b3: 64 j4 x 16 kg of 8 k --------------------
        {
            const int j4 = tid & 63;
            const int kg = tid >> 6;      // 0..15
            float4 acc = make_float4(0.f, 0.f, 0.f, 0.f);
#pragma unroll
            for (int i = 0; i < 8; ++i) {
                const int k = kg * 8 + i;
                float4 w = __ldg(&wo34[(size_t)k * 64 + j4]);
                float  s = s_h2[k];
                acc.x += s * w.x; acc.y += s * w.y; acc.z += s * w.z; acc.w += s * w.w;
            }
            s_red[kg * 64 + j4] = acc;
        }
        __syncthreads();
        if (tid < 64) {
            float4 acc = __ldg(&b34[tid]);
#pragma unroll
            for (int g = 0; g < 16; ++g) {
                float4 v = s_red[g * 64 + tid];
                acc.x += v.x; acc.y += v.y; acc.z += v.z; acc.w += v.w;
            }
            out4[(size_t)b * 64 + tid] = acc;
        }
    }
}

// ---------------------------------------------------------------------------
// Inputs: 0 feature, 1 lidar, 2 conv1_w, 3 conv2_w, 4 wq, 5 wk, 6 wv,
//         7 wo1, 8 b1, 9 wo2, 10 b2, 11 wo3, 12 b3
// ---------------------------------------------------------------------------
extern "C" void kernel_launch(void* const* d_in, const int* in_sizes, int n_in,
                              void* d_out, int out_size)
{
    const float4* lidar4 = (const float4*)d_in[1];
    const float*  wv     = (const float*)d_in[6];
    const float4* wo14   = (const float4*)d_in[7];
    const float4* b14    = (const float4*)d_in[8];
    const float4* wo24   = (const float4*)d_in[9];
    const float4* b24    = (const float4*)d_in[10];
    const float4* wo34   = (const float4*)d_in[11];
    const float4* b34    = (const float4*)d_in[12];
    float4* out4 = (float4*)d_out;

    void* sync_addr = nullptr;
    cudaGetSymbolAddress(&sync_addr, g_sync);
    cudaMemsetAsync(sync_addr, 0, sizeof(unsigned int));

    fused_kernel<<<TOTAL_BLOCKS, 1024>>>(lidar4, wv, wo14, b14,
                                         wo24, b24, wo34, b34, out4);
}

// round 5
// speedup vs baseline: 5.0293x; 5.0293x over previous
#include <cuda_runtime.h>

// Live computation: out = MLP( (mean_p lidar[b,p,:]) @ wv ).
// Attention is dead (zero-pad last query row -> uniform softmax -> mean of V).
//
// 3-kernel chain (stream-ordered, graph-capturable):
//   K1 reduce : lidar partial column sums           grid (16,64) x 256 thr
//   K2 bins   : mean fold + bins = mean @ wv        grid (16,8)  x 256 thr
//   K3 head   : h1 -> h2 -> out (tiny MLP)          grid 16      x 1024 thr

#define BATCH     16
#define N_POINTS  4096
#define LIDAR_C   256
#define C4        (LIDAR_C / 4)           // 64
#define D_MODEL   1024
#define H1        128
#define BIN_SIZE  256
#define SPLIT     64
#define PTS_PER_BLK (N_POINTS / SPLIT)    // 64

__device__ float4 g_partial[SPLIT * BATCH * C4];   // [64][16][64] f4 = 1 MB
__device__ float4 g_bins[BATCH * (D_MODEL / 4)];   // [16][256] f4

// ---------------------------------------------------------------------------
// K1: partial column sums of lidar (DRAM-bound, 67 MB). Proven config.
// ---------------------------------------------------------------------------
__global__ void __launch_bounds__(256)
lidar_reduce_kernel(const float4* __restrict__ lidar4)
{
    const int b  = blockIdx.x;
    const int s  = blockIdx.y;
    const int c4 = threadIdx.x & 63;
    const int r  = threadIdx.x >> 6;

    const float4* base = lidar4
        + ((size_t)b * N_POINTS + (size_t)s * PTS_PER_BLK + (size_t)r * 16) * C4 + c4;

    float4 acc = make_float4(0.f, 0.f, 0.f, 0.f);
#pragma unroll
    for (int i = 0; i < 16; ++i) {
        float4 v = base[(size_t)i * C4];
        acc.x += v.x; acc.y += v.y; acc.z += v.z; acc.w += v.w;
    }

    __shared__ float4 sp[4][C4];
    sp[r][c4] = acc;
    __syncthreads();

    if (r == 0) {
        float4 a = sp[0][c4], bb = sp[1][c4], c = sp[2][c4], d = sp[3][c4];
        float4 t;
        t.x = (a.x + bb.x) + (c.x + d.x);
        t.y = (a.y + bb.y) + (c.y + d.y);
        t.z = (a.z + bb.z) + (c.z + d.z);
        t.w = (a.w + bb.w) + (c.w + d.w);
        g_partial[((size_t)s * BATCH + b) * C4 + c4] = t;
    }
}

// ---------------------------------------------------------------------------
// K2: fold partials -> mean, then bins[b][j-range] = mean @ wv.
// grid (16 batches, 8 j-chunks of 128), 256 threads.
// Per block: thread = (j4 lane 0..31, kg 0..7); 32 f4 LDGs/thread.
// ---------------------------------------------------------------------------
__global__ void __launch_bounds__(256)
bins_kernel(const float4* __restrict__ wv4)      // [256][256] f4
{
    const int b   = blockIdx.x;
    const int jq  = blockIdx.y;                  // 0..7, 32 f4 each
    const int tid = threadIdx.x;

    __shared__ float4 sp[4][C4];
    __shared__ float  s_mean[LIDAR_C];
    __shared__ float4 s_br[8][32];

    // fold 64 partials -> mean (16 f4 loads per thread)
    {
        const int c4 = tid & 63;
        const int sg = tid >> 6;                 // 0..3
        const float4* p = g_partial + (size_t)b * C4 + c4;
        float4 acc = make_float4(0.f, 0.f, 0.f, 0.f);
#pragma unroll
        for (int i = 0; i < 16; ++i) {
            float4 v = p[(size_t)(sg * 16 + i) * (BATCH * C4)];
            acc.x += v.x; acc.y += v.y; acc.z += v.z; acc.w += v.w;
        }
        sp[sg][c4] = acc;
    }
    __syncthreads();
    if (tid < C4) {
        float4 a = sp[0][tid], bb = sp[1][tid], c = sp[2][tid], d = sp[3][tid];
        const float inv = 1.0f / (float)N_POINTS;
        s_mean[tid * 4 + 0] = ((a.x + bb.x) + (c.x + d.x)) * inv;
        s_mean[tid * 4 + 1] = ((a.y + bb.y) + (c.y + d.y)) * inv;
        s_mean[tid * 4 + 2] = ((a.z + bb.z) + (c.z + d.z)) * inv;
        s_mean[tid * 4 + 3] = ((a.w + bb.w) + (c.w + d.w)) * inv;
    }
    __syncthreads();

    // bins: 32 j4 x 8 k-groups of 32 c
    {
        const int j4 = tid & 31;
        const int kg = tid >> 5;                 // 0..7
        const float4* w = wv4 + (size_t)(kg * 32) * 256 + jq * 32 + j4;
        const float*  m = s_mean + kg * 32;
        float4 acc = make_float4(0.f, 0.f, 0.f, 0.f);
#pragma unroll 8
        for (int k = 0; k < 32; ++k) {
            float4 v = __ldg(&w[(size_t)k * 256]);
            float  s = m[k];
            acc.x += s * v.x; acc.y += s * v.y; acc.z += s * v.z; acc.w += s * v.w;
        }
        s_br[kg][j4] = acc;
    }
    __syncthreads();
    if (tid < 32) {
        float4 acc = make_float4(0.f, 0.f, 0.f, 0.f);
#pragma unroll
        for (int g = 0; g < 8; ++g) {
            float4 v = s_br[g][tid];
            acc.x += v.x; acc.y += v.y; acc.z += v.z; acc.w += v.w;
        }
        g_bins[(size_t)b * 256 + jq * 32 + tid] = acc;
    }
}

// ---------------------------------------------------------------------------
// K3: per-batch tiny MLP. grid 16, 1024 threads.
// ---------------------------------------------------------------------------
__global__ void __launch_bounds__(1024)
head_kernel(const float4* __restrict__ wo14,   // [1024][32] f4
            const float4* __restrict__ b14,    // [32] f4
            const float4* __restrict__ wo24,   // [128][32] f4
            const float4* __restrict__ b24,    // [32] f4
            const float4* __restrict__ wo34,   // [128][64] f4
            const float4* __restrict__ b34,    // [64] f4
            float4*       __restrict__ out4)   // [16][64] f4
{
    const int b   = blockIdx.x;
    const int tid = threadIdx.x;

    __shared__ float  s_bins[D_MODEL];
    __shared__ float  s_h1[H1];
    __shared__ float  s_h2[H1];
    __shared__ float4 s_red[1024];

    if (tid < 256) {
        float4 v = g_bins[(size_t)b * 256 + tid];
        s_bins[tid * 4 + 0] = v.x;
        s_bins[tid * 4 + 1] = v.y;
        s_bins[tid * 4 + 2] = v.z;
        s_bins[tid * 4 + 3] = v.w;
    }
    __syncthreads();

    // h1 = lrelu(bins @ wo1 + b1): 32 j4 x 32 kg of 32 k
    {
        const int j4 = tid & 31;
        const int kg = tid >> 5;
        const float4* w = wo14 + (size_t)(kg * 32) * 32 + j4;
        const float*  m = s_bins + kg * 32;
        float4 acc = make_float4(0.f, 0.f, 0.f, 0.f);
#pragma unroll 8
        for (int k = 0; k < 32; ++k) {
            float4 v = __ldg(&w[(size_t)k * 32]);
            float  s = m[k];
            acc.x += s * v.x; acc.y += s * v.y; acc.z += s * v.z; acc.w += s * v.w;
        }
        s_red[kg * 32 + j4] = acc;
    }
    __syncthreads();
    if (tid < 32) {
        float4 acc = __ldg(&b14[tid]);
#pragma unroll
        for (int g = 0; g < 32; ++g) {
            float4 v = s_red[g * 32 + tid];
            acc.x += v.x; acc.y += v.y; acc.z += v.z; acc.w += v.w;
        }
        s_h1[tid * 4 + 0] = (acc.x > 0.f) ? acc.x : 0.01f * acc.x;
        s_h1[tid * 4 + 1] = (acc.y > 0.f) ? acc.y : 0.01f * acc.y;
        s_h1[tid * 4 + 2] = (acc.z > 0.f) ? acc.z : 0.01f * acc.z;
        s_h1[tid * 4 + 3] = (acc.w > 0.f) ? acc.w : 0.01f * acc.w;
    }
    __syncthreads();

    // h2 = lrelu(h1 @ wo2 + b2): 32 j4 x 32 kg of 4 k
    {
        const int j4 = tid & 31;
        const int kg = tid >> 5;
        const float4* w = wo24 + (size_t)(kg * 4) * 32 + j4;
        const float*  m = s_h1 + kg * 4;
        float4 acc = make_float4(0.f, 0.f, 0.f, 0.f);
#pragma unroll
        for (int k = 0; k < 4; ++k) {
            float4 v = __ldg(&w[(size_t)k * 32]);
            float  s = m[k];
            acc.x += s * v.x; acc.y += s * v.y; acc.z += s * v.z; acc.w += s * v.w;
        }
        s_red[kg * 32 + j4] = acc;
    }
    __syncthreads();
    if (tid < 32) {
        float4 acc = __ldg(&b24[tid]);
#pragma unroll
        for (int g = 0; g < 32; ++g) {
            float4 v = s_red[g * 32 + tid];
            acc.x += v.x; acc.y += v.y; acc.z += v.z; acc.w += v.w;
        }
        s_h2[tid * 4 + 0] = (acc.x > 0.f) ? acc.x : 0.01f * acc.x;
        s_h2[tid * 4 + 1] = (acc.y > 0.f) ? acc.y : 0.01f * acc.y;
        s_h2[tid * 4 + 2] = (acc.z > 0.f) ? acc.z : 0.01f * acc.z;
        s_h2[tid * 4 + 3] = (acc.w > 0.f) ? acc.w : 0.01f * acc.w;
    }
    __syncthreads();

    // out = h2 @ wo3 + b3: 64 j4 x 16 kg of 8 k
    {
        const int j4 = tid & 63;
        const int kg = tid >> 6;
        const float4* w = wo34 + (size_t)(kg * 8) * 64 + j4;
        const float*  m = s_h2 + kg * 8;
        float4 acc = make_float4(0.f, 0.f, 0.f, 0.f);
#pragma unroll
        for (int k = 0; k < 8; ++k) {
            float4 v = __ldg(&w[(size_t)k * 64]);
            float  s = m[k];
            acc.x += s * v.x; acc.y += s * v.y; acc.z += s * v.z; acc.w += s * v.w;
        }
        s_red[kg * 64 + j4] = acc;
    }
    __syncthreads();
    if (tid < 64) {
        float4 acc = __ldg(&b34[tid]);
#pragma unroll
        for (int g = 0; g < 16; ++g) {
            float4 v = s_red[g * 64 + tid];
            acc.x += v.x; acc.y += v.y; acc.z += v.z; acc.w += v.w;
        }
        out4[(size_t)b * 64 + tid] = acc;
    }
}

// ---------------------------------------------------------------------------
// Inputs: 0 feature, 1 lidar, 2 conv1_w, 3 conv2_w, 4 wq, 5 wk, 6 wv,
//         7 wo1, 8 b1, 9 wo2, 10 b2, 11 wo3, 12 b3
// ---------------------------------------------------------------------------
extern "C" void kernel_launch(void* const* d_in, const int* in_sizes, int n_in,
                              void* d_out, int out_size)
{
    const float4* lidar4 = (const float4*)d_in[1];
    const float4* wv4    = (const float4*)d_in[6];
    const float4* wo14   = (const float4*)d_in[7];
    const float4* b14    = (const float4*)d_in[8];
    const float4* wo24   = (const float4*)d_in[9];
    const float4* b24    = (const float4*)d_in[10];
    const float4* wo34   = (const float4*)d_in[11];
    const float4* b34    = (const float4*)d_in[12];
    float4* out4 = (float4*)d_out;

    lidar_reduce_kernel<<<dim3(BATCH, SPLIT), 256>>>(lidar4);
    bins_kernel<<<dim3(BATCH, 8), 256>>>(wv4);
    head_kernel<<<BATCH, 1024>>>(wo14, b14, wo24, b24, wo34, b34, out4);
}

// round 6
// speedup vs baseline: 5.2141x; 1.0367x over previous
#include <cuda_runtime.h>

// Live computation: out = MLP( (mean_p lidar[b,p,:]) @ wv ).
// Attention is dead (zero-pad last query row -> uniform softmax -> mean of V).
//
// 3-kernel chain:
//   K1 reduce  : lidar partial column sums              grid (16,64) x 256
//   K2 bins+h1 : mean fold; bins chunk = mean@wv[:,jq]; grid (16,8)  x 256
//                h1 partial = bins_chunk @ wo1[chunk,:]
//   K3 head    : fold h1 partials -> lrelu -> h2 -> out grid 16      x 256

#define BATCH     16
#define N_POINTS  4096
#define LIDAR_C   256
#define C4        (LIDAR_C / 4)           // 64
#define D_MODEL   1024
#define H1        128
#define BIN_SIZE  256
#define SPLIT     64
#define PTS_PER_BLK (N_POINTS / SPLIT)    // 64

__device__ float4 g_partial[SPLIT * BATCH * C4];   // [64][16][64] f4 = 1 MB
__device__ float4 g_h1p[BATCH * 8 * (H1 / 4)];     // [16][8][32] f4

// ---------------------------------------------------------------------------
// K1: partial column sums of lidar (DRAM-bound, 67 MB). __ldcs: read-once.
// ---------------------------------------------------------------------------
__global__ void __launch_bounds__(256)
lidar_reduce_kernel(const float4* __restrict__ lidar4)
{
    const int b  = blockIdx.x;
    const int s  = blockIdx.y;
    const int c4 = threadIdx.x & 63;
    const int r  = threadIdx.x >> 6;

    const float4* base = lidar4
        + ((size_t)b * N_POINTS + (size_t)s * PTS_PER_BLK + (size_t)r * 16) * C4 + c4;

    float4 acc = make_float4(0.f, 0.f, 0.f, 0.f);
#pragma unroll
    for (int i = 0; i < 16; ++i) {
        float4 v = __ldcs(&base[(size_t)i * C4]);
        acc.x += v.x; acc.y += v.y; acc.z += v.z; acc.w += v.w;
    }

    __shared__ float4 sp[4][C4];
    sp[r][c4] = acc;
    __syncthreads();

    if (r == 0) {
        float4 a = sp[0][c4], bb = sp[1][c4], c = sp[2][c4], d = sp[3][c4];
        float4 t;
        t.x = (a.x + bb.x) + (c.x + d.x);
        t.y = (a.y + bb.y) + (c.y + d.y);
        t.z = (a.z + bb.z) + (c.z + d.z);
        t.w = (a.w + bb.w) + (c.w + d.w);
        g_partial[((size_t)s * BATCH + b) * C4 + c4] = t;
    }
}

// ---------------------------------------------------------------------------
// K2: per (batch, j-chunk): fold partials -> mean; bins_chunk = mean @ wv
// columns [jq*128, jq*128+128); h1 partial = bins_chunk @ wo1 rows of chunk.
// ---------------------------------------------------------------------------
__global__ void __launch_bounds__(256)
bins_h1_kernel(const float4* __restrict__ wv4,     // [256][256] f4
               const float4* __restrict__ wo14)    // [1024][32] f4
{
    const int b   = blockIdx.x;
    const int jq  = blockIdx.y;                    // 0..7
    const int tid = threadIdx.x;
    const int j4  = tid & 31;
    const int kg  = tid >> 5;                      // 0..7

    __shared__ float4 sp[4][C4];
    __shared__ float  s_mean[LIDAR_C];
    __shared__ float  s_binsc[128];
    __shared__ float4 s_red[8][32];

    // ---- fold 64 partials -> mean -----------------------------------------
    {
        const int c4 = tid & 63;
        const int sg = tid >> 6;                   // 0..3
        const float4* p = g_partial + (size_t)b * C4 + c4;
        float4 acc = make_float4(0.f, 0.f, 0.f, 0.f);
#pragma unroll
        for (int i = 0; i < 16; ++i) {
            float4 v = p[(size_t)(sg * 16 + i) * (BATCH * C4)];
            acc.x += v.x; acc.y += v.y; acc.z += v.z; acc.w += v.w;
        }
        sp[sg][c4] = acc;
    }
    __syncthreads();
    if (tid < C4) {
        float4 a = sp[0][tid], bb = sp[1][tid], c = sp[2][tid], d = sp[3][tid];
        const float inv = 1.0f / (float)N_POINTS;
        s_mean[tid * 4 + 0] = ((a.x + bb.x) + (c.x + d.x)) * inv;
        s_mean[tid * 4 + 1] = ((a.y + bb.y) + (c.y + d.y)) * inv;
        s_mean[tid * 4 + 2] = ((a.z + bb.z) + (c.z + d.z)) * inv;
        s_mean[tid * 4 + 3] = ((a.w + bb.w) + (c.w + d.w)) * inv;
    }
    __syncthreads();

    // ---- bins chunk: 32 j4 x 8 kg of 32 k ----------------------------------
    {
        const float4* w = wv4 + (size_t)(kg * 32) * 256 + jq * 32 + j4;
        const float*  m = s_mean + kg * 32;
        float4 acc = make_float4(0.f, 0.f, 0.f, 0.f);
#pragma unroll 8
        for (int k = 0; k < 32; ++k) {
            float4 v = __ldg(&w[(size_t)k * 256]);
            float  s = m[k];
            acc.x += s * v.x; acc.y += s * v.y; acc.z += s * v.z; acc.w += s * v.w;
        }
        s_red[kg][j4] = acc;
    }
    __syncthreads();
    if (tid < 32) {
        float4 acc = make_float4(0.f, 0.f, 0.f, 0.f);
#pragma unroll
        for (int g = 0; g < 8; ++g) {
            float4 v = s_red[g][tid];
            acc.x += v.x; acc.y += v.y; acc.z += v.z; acc.w += v.w;
        }
        s_binsc[tid * 4 + 0] = acc.x;
        s_binsc[tid * 4 + 1] = acc.y;
        s_binsc[tid * 4 + 2] = acc.z;
        s_binsc[tid * 4 + 3] = acc.w;
    }
    __syncthreads();

    // ---- h1 partial: 32 j4 x 8 kg of 16 k ----------------------------------
    {
        const float4* w = wo14 + ((size_t)jq * 128 + kg * 16) * 32 + j4;
        const float*  m = s_binsc + kg * 16;
        float4 acc = make_float4(0.f, 0.f, 0.f, 0.f);
#pragma unroll
        for (int k = 0; k < 16; ++k) {
            float4 v = __ldg(&w[(size_t)k * 32]);
            float  s = m[k];
            acc.x += s * v.x; acc.y += s * v.y; acc.z += s * v.z; acc.w += s * v.w;
        }
        s_red[kg][j4] = acc;
    }
    __syncthreads();
    if (tid < 32) {
        float4 acc = make_float4(0.f, 0.f, 0.f, 0.f);
#pragma unroll
        for (int g = 0; g < 8; ++g) {
            float4 v = s_red[g][tid];
            acc.x += v.x; acc.y += v.y; acc.z += v.z; acc.w += v.w;
        }
        g_h1p[((size_t)b * 8 + jq) * 32 + tid] = acc;
    }
}

// ---------------------------------------------------------------------------
// K3: per-batch tail: fold h1 partials + b1 -> lrelu -> h2 -> out.
// grid 16, 256 threads.
// ---------------------------------------------------------------------------
__global__ void __launch_bounds__(256)
head_kernel(const float4* __restrict__ b14,    // [32] f4
            const float4* __restrict__ wo24,   // [128][32] f4
            const float4* __restrict__ b24,    // [32] f4
            const float4* __restrict__ wo34,   // [128][64] f4
            const float4* __restrict__ b34,    // [64] f4
            float4*       __restrict__ out4)   // [16][64] f4
{
    const int b   = blockIdx.x;
    const int tid = threadIdx.x;

    __shared__ float4 s_p[256];      // h1 partials / reused as reduce buffer
    __shared__ float  s_h1[H1];
    __shared__ float  s_h2[H1];

    s_p[tid] = g_h1p[(size_t)b * 256 + tid];
    __syncthreads();

    // h1 = lrelu(sum_g partials + b1)
    if (tid < 32) {
        float4 acc = __ldg(&b14[tid]);
#pragma unroll
        for (int g = 0; g < 8; ++g) {
            float4 v = s_p[g * 32 + tid];
            acc.x += v.x; acc.y += v.y; acc.z += v.z; acc.w += v.w;
        }
        s_h1[tid * 4 + 0] = (acc.x > 0.f) ? acc.x : 0.01f * acc.x;
        s_h1[tid * 4 + 1] = (acc.y > 0.f) ? acc.y : 0.01f * acc.y;
        s_h1[tid * 4 + 2] = (acc.z > 0.f) ? acc.z : 0.01f * acc.z;
        s_h1[tid * 4 + 3] = (acc.w > 0.f) ? acc.w : 0.01f * acc.w;
    }
    __syncthreads();

    // h2 = lrelu(h1 @ wo2 + b2): 32 j4 x 8 kg of 16 k -> s_p[kg*32+j4]
    {
        const int j4 = tid & 31;
        const int kg = tid >> 5;                 // 0..7
        const float4* w = wo24 + (size_t)(kg * 16) * 32 + j4;
        const float*  m = s_h1 + kg * 16;
        float4 acc = make_float4(0.f, 0.f, 0.f, 0.f);
#pragma unroll
        for (int k = 0; k < 16; ++k) {
            float4 v = __ldg(&w[(size_t)k * 32]);
            float  s = m[k];
            acc.x += s * v.x; acc.y += s * v.y; acc.z += s * v.z; acc.w += s * v.w;
        }
        __syncthreads();
        s_p[kg * 32 + j4] = acc;
    }
    __syncthreads();
    if (tid < 32) {
        float4 acc = __ldg(&b24[tid]);
#pragma unroll
        for (int g = 0; g < 8; ++g) {
            float4 v = s_p[g * 32 + tid];
            acc.x += v.x; acc.y += v.y; acc.z += v.z; acc.w += v.w;
        }
        s_h2[tid * 4 + 0] = (acc.x > 0.f) ? acc.x : 0.01f * acc.x;
        s_h2[tid * 4 + 1] = (acc.y > 0.f) ? acc.y : 0.01f * acc.y;
        s_h2[tid * 4 + 2] = (acc.z > 0.f) ? acc.z : 0.01f * acc.z;
        s_h2[tid * 4 + 3] = (acc.w > 0.f) ? acc.w : 0.01f * acc.w;
    }
    __syncthreads();

    // out = h2 @ wo3 + b3: 64 j4 x 4 kg of 32 k -> s_p[kg*64+j4]
    {
        const int j4 = tid & 63;
        const int kg = tid >> 6;                 // 0..3
        const float4* w = wo34 + (size_t)(kg * 32) * 64 + j4;
        const float*  m = s_h2 + kg * 32;
        float4 acc = make_float4(0.f, 0.f, 0.f, 0.f);
#pragma unroll 8
        for (int k = 0; k < 32; ++k) {
            float4 v = __ldg(&w[(size_t)k * 64]);
            float  s = m[k];
            acc.x += s * v.x; acc.y += s * v.y; acc.z += s * v.z; acc.w += s * v.w;
        }
        __syncthreads();
        s_p[kg * 64 + j4] = acc;
    }
    __syncthreads();
    if (tid < 64) {
        float4 acc = __ldg(&b34[tid]);
#pragma unroll
        for (int g = 0; g < 4; ++g) {
            float4 v = s_p[g * 64 + tid];
            acc.x += v.x; acc.y += v.y; acc.z += v.z; acc.w += v.w;
        }
        out4[(size_t)b * 64 + tid] = acc;
    }
}

// ---------------------------------------------------------------------------
// Inputs: 0 feature, 1 lidar, 2 conv1_w, 3 conv2_w, 4 wq, 5 wk, 6 wv,
//         7 wo1, 8 b1, 9 wo2, 10 b2, 11 wo3, 12 b3
// ---------------------------------------------------------------------------
extern "C" void kernel_launch(void* const* d_in, const int* in_sizes, int n_in,
                              void* d_out, int out_size)
{
    const float4* lidar4 = (const float4*)d_in[1];
    const float4* wv4    = (const float4*)d_in[6];
    const float4* wo14   = (const float4*)d_in[7];
    const float4* b14    = (const float4*)d_in[8];
    const float4* wo24   = (const float4*)d_in[9];
    const float4* b24    = (const float4*)d_in[10];
    const float4* wo34   = (const float4*)d_in[11];
    const float4* b34    = (const float4*)d_in[12];
    float4* out4 = (float4*)d_out;

    lidar_reduce_kernel<<<dim3(BATCH, SPLIT), 256>>>(lidar4);
    bins_h1_kernel<<<dim3(BATCH, 8), 256>>>(wv4, wo14);
    head_kernel<<<BATCH, 256>>>(b14, wo24, b24, wo34, b34, out4);
}